// round 2
// baseline (speedup 1.0000x reference)
#include <cuda_runtime.h>
#include <math.h>

// Problem constants
#define Dd   128
#define Kk   1024
#define Nn   4096
#define Bb   8
#define NIN  256

// Tiling
#define NT   64     // n-tile per CTA
#define KC   64     // k chunk
#define ZSS  132    // ze_s row stride (floats)
#define ESS  132    // emb_s row stride (floats)

#define ZQ_OFF    (Bb * Dd * Nn)            // 4194304 (end of zq region)
#define NUM_OFF   (Bb * Dd * Nn)            // numer starts here
#define DEN_OFF   (Bb * Dd * Nn + Kk * Dd)  // denom starts here

// Scratch (device globals; no allocation allowed)
__device__ float g_zsum[Kk * Dd];
__device__ float g_nsum[Kk];
__device__ float g_qsq[Kk];
__device__ float g_qsrt[Kk];

// ---------------------------------------------------------------------------
// Init: zero EMA scratch, compute per-code ||q||^2 and ||q||
// ---------------------------------------------------------------------------
__global__ void vq_init_kernel(const float* __restrict__ emb) {
    int k = blockIdx.x;      // 0..1023
    int d = threadIdx.x;     // 0..127
    float e = emb[k * Dd + d];
    g_zsum[k * Dd + d] = 0.f;
    float v = e * e;
    #pragma unroll
    for (int o = 16; o > 0; o >>= 1) v += __shfl_xor_sync(0xffffffffu, v, o);
    __shared__ float sred[4];
    if ((d & 31) == 0) sred[d >> 5] = v;
    __syncthreads();
    if (d == 0) {
        float q = sred[0] + sred[1] + sred[2] + sred[3];
        g_qsq[k] = q;
        g_qsrt[k] = sqrtf(q);
        g_nsum[k] = 0.f;
    }
}

__device__ __forceinline__ float dot4(float4 a, float4 b, float c) {
    return fmaf(a.x, b.x, fmaf(a.y, b.y, fmaf(a.z, b.z, fmaf(a.w, b.w, c))));
}

// ---------------------------------------------------------------------------
// Fused main kernel: ze GEMM -> distance GEMM + argmin -> gather + EMA scatter
// Shared layout (dynamic):
//   [0,8448)        ze_s  [64][132]
//   [8448,16896)    U: phaseA(Wc 128x36, zc 32x68) / emb_s[64][132] / red arrays
//   [16896,16960)   ze_sq[64]
//   [16960,17024)   s_srt[64]
//   [17024,17088)   ind_s[64] (int)
// ---------------------------------------------------------------------------
extern __shared__ float smem_f[];

__global__ void __launch_bounds__(256, 2)
vq_main_kernel(const float* __restrict__ z, const float* __restrict__ W,
               const float* __restrict__ emb, float* __restrict__ out)
{
    float* ze_s  = smem_f;
    float* U     = smem_f + NT * ZSS;
    float* Wc    = U;                    // 128*36 = 4608 floats
    float* zc    = U + 128 * 36;         // 32*68  = 2176 floats (fits in 8448)
    float* emb_s = U;                    // 64*132 = 8448 floats
    float* red_d2 = U;                   // 16*64
    float* red_dn = U + 1024;            // 16*64
    int*   red_id = (int*)(U + 2048);    // 16*64
    float* ze_sq = smem_f + 2 * NT * ZSS;        // 64
    float* s_srt = ze_sq + NT;                   // 64
    int*   ind_s = (int*)(s_srt + NT);           // 64

    const int tid = threadIdx.x;
    const int b   = blockIdx.y;
    const int n0  = blockIdx.x * NT;
    const float* zb = z + (size_t)b * NIN * Nn;

    // ================= Phase A: ze tile (128 d x 64 n) =================
    {
        const int tdA = tid >> 4;     // 0..15 -> 8 d rows
        const int tnA = tid & 15;     // 0..15 -> 4 n cols
        const int dA = tdA * 8;
        const int nA = tnA * 4;
        float acc[8][4];
        #pragma unroll
        for (int i = 0; i < 8; i++)
            #pragma unroll
            for (int j = 0; j < 4; j++) acc[i][j] = 0.f;

        for (int c0 = 0; c0 < NIN; c0 += 32) {
            // stage W chunk [128][32]
            {
                int c4 = (tid & 7) * 4;
                int dr = tid >> 3; // 0..31
                #pragma unroll
                for (int r = 0; r < 4; r++) {
                    int d = dr + 32 * r;
                    float4 w = *(const float4*)&W[(size_t)d * NIN + c0 + c4];
                    *(float4*)&Wc[d * 36 + c4] = w;
                }
            }
            // stage z chunk [32][64]
            {
                int q4 = (tid & 15) * 4;
                int ccr = tid >> 4; // 0..15
                #pragma unroll
                for (int r = 0; r < 2; r++) {
                    int cc = ccr + 16 * r;
                    float4 v = *(const float4*)&zb[(size_t)(c0 + cc) * Nn + n0 + q4];
                    *(float4*)&zc[cc * 68 + q4] = v;
                }
            }
            __syncthreads();
            #pragma unroll 2
            for (int cc = 0; cc < 32; cc += 4) {
                float4 w4[8], z4[4];
                #pragma unroll
                for (int i = 0; i < 8; i++)
                    w4[i] = *(const float4*)&Wc[(dA + i) * 36 + cc];
                #pragma unroll
                for (int u = 0; u < 4; u++)
                    z4[u] = *(const float4*)&zc[(cc + u) * 68 + nA];
                #pragma unroll
                for (int i = 0; i < 8; i++) {
                    float4 w = w4[i];
                    acc[i][0] = fmaf(w.x, z4[0].x, fmaf(w.y, z4[1].x, fmaf(w.z, z4[2].x, fmaf(w.w, z4[3].x, acc[i][0]))));
                    acc[i][1] = fmaf(w.x, z4[0].y, fmaf(w.y, z4[1].y, fmaf(w.z, z4[2].y, fmaf(w.w, z4[3].y, acc[i][1]))));
                    acc[i][2] = fmaf(w.x, z4[0].z, fmaf(w.y, z4[1].z, fmaf(w.z, z4[2].z, fmaf(w.w, z4[3].z, acc[i][2]))));
                    acc[i][3] = fmaf(w.x, z4[0].w, fmaf(w.y, z4[1].w, fmaf(w.z, z4[2].w, fmaf(w.w, z4[3].w, acc[i][3]))));
                }
            }
            __syncthreads();
        }
        // write transposed ze_s[n][d]
        #pragma unroll
        for (int j = 0; j < 4; j++) {
            int n = nA + j;
            float4 v0 = make_float4(acc[0][j], acc[1][j], acc[2][j], acc[3][j]);
            float4 v1 = make_float4(acc[4][j], acc[5][j], acc[6][j], acc[7][j]);
            *(float4*)&ze_s[n * ZSS + dA]     = v0;
            *(float4*)&ze_s[n * ZSS + dA + 4] = v1;
        }
    }
    __syncthreads();

    // per-n ||ze||^2 and ||ze||
    if (tid < NT) {
        const float* row = &ze_s[tid * ZSS];
        float s = 0.f;
        #pragma unroll 8
        for (int d = 0; d < Dd; d += 4) {
            float4 v = *(const float4*)&row[d];
            s += v.x * v.x + v.y * v.y + v.z * v.z + v.w * v.w;
        }
        ze_sq[tid] = s;
        s_srt[tid] = sqrtf(s);
    }
    __syncthreads();

    // ================= Phase B: distances + running argmin =================
    const int tk = tid >> 4;  // 0..15 -> 4 k rows
    const int tn = tid & 15;  // n's = tn + 16*j
    float bd2[4], bdn[4];
    int   bid_[4];
    float zsq_r[4], ssr_r[4];
    #pragma unroll
    for (int j = 0; j < 4; j++) {
        bd2[j] = __int_as_float(0x7f800000);  // +inf
        bdn[j] = 1.f;
        bid_[j] = 0;
        zsq_r[j] = ze_sq[tn + 16 * j];
        ssr_r[j] = s_srt[tn + 16 * j];
    }

    for (int kc = 0; kc < Kk; kc += KC) {
        // stage emb chunk [64][128]
        {
            int row = tid >> 5;        // 0..7
            int c4 = (tid & 31) * 4;   // 0..124
            #pragma unroll
            for (int r = 0; r < 8; r++) {
                int kk = row + 8 * r;
                float4 v = *(const float4*)&emb[(size_t)(kc + kk) * Dd + c4];
                *(float4*)&emb_s[kk * ESS + c4] = v;
            }
        }
        __syncthreads();

        float dot[4][4];
        #pragma unroll
        for (int i = 0; i < 4; i++)
            #pragma unroll
            for (int j = 0; j < 4; j++) dot[i][j] = 0.f;

        #pragma unroll 4
        for (int d = 0; d < Dd; d += 4) {
            float4 a[4], qv[4];
            #pragma unroll
            for (int i = 0; i < 4; i++)
                a[i] = *(const float4*)&emb_s[(tk * 4 + i) * ESS + d];
            #pragma unroll
            for (int j = 0; j < 4; j++)
                qv[j] = *(const float4*)&ze_s[(tn + 16 * j) * ZSS + d];
            #pragma unroll
            for (int i = 0; i < 4; i++)
                #pragma unroll
                for (int j = 0; j < 4; j++)
                    dot[i][j] = dot4(a[i], qv[j], dot[i][j]);
        }

        // epilogue: scaled-distance compare via cross-multiplication (no sqrt/div)
        #pragma unroll
        for (int i = 0; i < 4; i++) {
            int k = kc + tk * 4 + i;
            float qsq = g_qsq[k];
            float qsr = g_qsrt[k];
            #pragma unroll
            for (int j = 0; j < 4; j++) {
                float d2 = fmaf(-2.f, dot[i][j], zsq_r[j] + qsq);
                d2 = fmaxf(d2, 0.f);
                float den = ssr_r[j] + qsr;
                float dn2 = den * den;
                float lhs = d2 * bdn[j];
                float rhs = bd2[j] * dn2;
                if (lhs < rhs || (lhs == rhs && k < bid_[j])) {
                    bd2[j] = d2; bdn[j] = dn2; bid_[j] = k;
                }
            }
        }
        __syncthreads();  // done with emb_s before next stage / red overwrite
    }

    // cross-thread argmin reduce (16 tk groups per n)
    #pragma unroll
    for (int j = 0; j < 4; j++) {
        int n = tn + 16 * j;
        red_d2[tk * NT + n] = bd2[j];
        red_dn[tk * NT + n] = bdn[j];
        red_id[tk * NT + n] = bid_[j];
    }
    __syncthreads();
    if (tid < NT) {
        int n = tid;
        float cd2 = red_d2[n], cdn = red_dn[n];
        int ci = red_id[n];
        #pragma unroll
        for (int t = 1; t < 16; t++) {
            float d2 = red_d2[t * NT + n];
            float dn = red_dn[t * NT + n];
            int   ii = red_id[t * NT + n];
            float lhs = d2 * cdn, rhs = cd2 * dn;
            if (lhs < rhs || (lhs == rhs && ii < ci)) { cd2 = d2; cdn = dn; ci = ii; }
        }
        ind_s[n] = ci;
        atomicAdd(&g_nsum[ci], 1.0f);
    }
    __syncthreads();

    // ================= Epilogue: gather zq + EMA scatter =================
    {
        int nn = tid & 63;
        int dblk = tid >> 6;  // 0..3
        int ci = ind_s[nn];
        const float* erow = emb + (size_t)ci * Dd;
        float* zsr = g_zsum + (size_t)ci * Dd;
        float* oz = out + (size_t)b * Dd * Nn + (size_t)(n0 + nn);
        const float* zrow = &ze_s[nn * ZSS];
        #pragma unroll 4
        for (int dd = 0; dd < 32; dd++) {
            int d = dblk * 32 + dd;
            oz[(size_t)d * Nn] = erow[d];
            atomicAdd(&zsr[d], zrow[d]);
        }
    }
}

// ---------------------------------------------------------------------------
// Finalize EMA outputs
// ---------------------------------------------------------------------------
__global__ void vq_ema_kernel(const float* __restrict__ numer,
                              const float* __restrict__ denom,
                              float* __restrict__ out)
{
    int i = blockIdx.x * blockDim.x + threadIdx.x;  // 0..131071
    out[NUM_OFF + i] = 0.99f * numer[i] + 0.01f * g_zsum[i];
    if (i < Kk)
        out[DEN_OFF + i] = 0.99f * denom[i] + 0.01f * g_nsum[i];
}

// ---------------------------------------------------------------------------
extern "C" void kernel_launch(void* const* d_in, const int* in_sizes, int n_in,
                              void* d_out, int out_size)
{
    const float* z     = (const float*)d_in[0];
    const float* W     = (const float*)d_in[1];
    const float* emb   = (const float*)d_in[2];
    const float* numer = (const float*)d_in[3];
    const float* denom = (const float*)d_in[4];
    float* out = (float*)d_out;

    const int smem_bytes = (2 * NT * ZSS + 2 * NT) * 4 + NT * 4;  // 68352
    cudaFuncSetAttribute(vq_main_kernel,
                         cudaFuncAttributeMaxDynamicSharedMemorySize, smem_bytes);

    vq_init_kernel<<<Kk, Dd>>>(emb);
    dim3 grid(Nn / NT, Bb);
    vq_main_kernel<<<grid, 256, smem_bytes>>>(z, W, emb, out);
    vq_ema_kernel<<<(Kk * Dd) / 256, 256>>>(numer, denom, out);
}